// round 13
// baseline (speedup 1.0000x reference)
#include <cuda_runtime.h>

// Problem constants
#define TT 1024   // T: tickers / states
#define MM 8      // M: mesa rank
#define NN 32768  // N: samples
#define DD 32     // D: input dim
#define HH 64     // H: hidden dim
#define SS 2177   // S = H*D + H + O*H + O
#define SP 2192   // padded state row stride (float4-aligned)
#define CAP 128   // bucket capacity per ticker

#define STATE_BLOCKS 288   // 32-ticker tiles x 9 dst-tiles (best measured)
#define SCAT_BLOCKS  32    // 32768 / (4 * 256)

// Scratch (__device__ globals, zero-initialized at module load).
// d_bucket stores n+1 (0 = never written). Slots beyond cnt are never
// written in any run (counter reset each run by k_compute tid 0), so the
// zero-tag invariant holds across graph replays.
__device__ int   d_count[TT];
__device__ int   d_bucket[TT * CAP];
__device__ float d_states[TT * SP];   // rows stored in PERMUTED (j*64+h) order

__device__ __forceinline__ unsigned long long fma2(
    unsigned long long a, unsigned long long b, unsigned long long c) {
    unsigned long long d;
    asm("fma.rn.f32x2 %0, %1, %2, %3;" : "=l"(d) : "l"(a), "l"(b), "l"(c));
    return d;
}

// ---------------------------------------------------------------------------
// k_prep: blocks [0,288) build effective states in PERMUTED layout:
//   row[d], d = j*64 + h  holds  w1_eff[h][j]  (d < 2048);
//   row[d] = state[d] for d in [2048,2177) (b1 | w2 | b2).
// blocks [288,320): bucket-scatter samples by ticker (stores n+1 tags).
// ---------------------------------------------------------------------------
__global__ __launch_bounds__(256) void k_prep(
    const int*   __restrict__ ticker,
    const float* __restrict__ mesa,   // (M, T)
    const float* __restrict__ meta,   // (S, M)
    const float* __restrict__ bias,   // (S,)
    const float* __restrict__ base)   // (S,)
{
    int b   = blockIdx.x;
    int tid = threadIdx.x;

    if (b < STATE_BLOCKS) {
        __shared__ float4 sc4[32][2];     // mesa coeffs for 32 tickers
        int tt = b / 9, st = b % 9;
        int t0 = tt * 32;
        {
            int m = tid >> 5, i = tid & 31;
            ((float*)sc4)[i * 8 + m] = mesa[m * TT + t0 + i];
        }
        __syncthreads();

        int d = st * 256 + tid;           // destination index in permuted row
        int s;
        bool ok = true;
        if (d < 2048) {                   // w1: d = j*64 + h  <->  s = h*32 + j
            int h = d & 63, j = d >> 6;
            s = h * 32 + j;
        } else {
            s = d;
            ok = (d < SS);
        }
        if (ok) {
            const float4* m4 = (const float4*)(meta + s * MM);
            float4 a = m4[0], bq = m4[1];
            float bb = base[s] + bias[s];
#pragma unroll
            for (int i = 0; i < 32; i++) {
                float4 c0 = sc4[i][0];    // broadcast LDS.128
                float4 c1 = sc4[i][1];
                float v = bb
                    + c0.x * a.x + c0.y * a.y + c0.z * a.z + c0.w * a.w
                    + c1.x * bq.x + c1.y * bq.y + c1.z * bq.z + c1.w * bq.w;
                d_states[(t0 + i) * SP + d] = v;   // coalesced over d
            }
        }
    } else {
        int idx = (b - STATE_BLOCKS) * 256 + tid;
        int4 v = ((const int4*)ticker)[idx];
        int n0 = idx * 4;
        int p;
        p = atomicAdd(&d_count[v.x], 1); if (p < CAP) d_bucket[v.x * CAP + p] = n0 + 1;
        p = atomicAdd(&d_count[v.y], 1); if (p < CAP) d_bucket[v.y * CAP + p] = n0 + 2;
        p = atomicAdd(&d_count[v.z], 1); if (p < CAP) d_bucket[v.z * CAP + p] = n0 + 3;
        p = atomicAdd(&d_count[v.w], 1); if (p < CAP) d_bucket[v.w * CAP + p] = n0 + 4;
    }
}

// ---------------------------------------------------------------------------
// k_compute: ONE CTA of 64 threads per ticker; weight row loaded
// cooperatively ONCE (half the per-warp prologue of R5, same L2 traffic),
// then the two warps run FULLY INDEPENDENTLY (no further barriers):
// warp g owns bucket slots [32g, ...) stride 64, with its own s_x/s_n half.
// Inner loop identical to the best-measured R5 shape: sample-per-lane,
// 32 f32x2 hidden accumulators, scalar stride-33 x reads, broadcast LDS.128
// weight reads. Work derived from n+1 validity tags (d_count never read).
// ---------------------------------------------------------------------------
__global__ __launch_bounds__(64) void k_compute(
    const float* __restrict__ x,
    float* __restrict__ out)
{
    __shared__ __align__(16) float s_w[2180];
    __shared__ float s_x[2][32 * 33];     // per-warp staging, stride 33
    __shared__ int   s_n[2][32];

    int t    = blockIdx.x;
    int tid  = threadIdx.x;
    int g    = tid >> 5;
    int lane = tid & 31;

    if (tid == 0) d_count[t] = 0;         // reset for next replay

    // Cooperative coalesced copy of the permuted state row (545 float4).
    const float4* row4 = (const float4*)(d_states + (size_t)t * SP);
    float4* s_w4 = (float4*)s_w;
#pragma unroll
    for (int i = 0; i < 9; i++) {
        int idx = tid + i * 64;
        if (idx < 545) s_w4[idx] = row4[idx];
    }
    __syncthreads();                      // the ONLY block-wide barrier

    const int* bucket = d_bucket + t * CAP;
    if (bucket[g * 32] == 0) return;      // this warp has no work

    const unsigned long long* b1p =
        (const unsigned long long*)(s_w + 2048);     // b1 as f32x2 pairs
    float b2 = s_w[2176];
    float* sx = s_x[g];
    int*   sn = s_n[g];

    for (int slot0 = g * 32; slot0 < CAP; slot0 += 64) {
        int v = bucket[slot0 + lane];
        unsigned mask = __ballot_sync(0xffffffffu, v != 0);
        if (mask == 0) break;             // contiguous fill: later slots empty
        bool valid = v != 0;
        int n = valid ? v - 1 : 0;

        __syncwarp();                     // prior iteration done with sn/sx
        sn[lane] = n;
        __syncwarp();
#pragma unroll
        for (int k = 0; k < 32; k++) {
            int nk = sn[k];                           // broadcast LDS
            sx[k * 33 + lane] = x[nk * DD + lane];    // coalesced 128B rows
        }
        __syncwarp();

        unsigned long long acc[32];
#pragma unroll
        for (int hp = 0; hp < 32; hp++) acc[hp] = b1p[hp];

#pragma unroll 8
        for (int j = 0; j < 32; j++) {
            float xj = sx[lane * 33 + j];             // scalar LDS, conflict-free
            unsigned long long xd;
            asm("mov.b64 %0, {%1, %1};" : "=l"(xd) : "f"(xj));
            const ulonglong2* wr = (const ulonglong2*)(s_w + j * 64);
#pragma unroll
            for (int hq = 0; hq < 16; hq++) {
                ulonglong2 w = wr[hq];                // broadcast LDS.128
                acc[2 * hq]     = fma2(w.x, xd, acc[2 * hq]);
                acc[2 * hq + 1] = fma2(w.y, xd, acc[2 * hq + 1]);
            }
        }

        float o = b2;
#pragma unroll
        for (int hp = 0; hp < 32; hp++) {
            float lo = __uint_as_float((unsigned)(acc[hp] & 0xffffffffu));
            float hi = __uint_as_float((unsigned)(acc[hp] >> 32));
            o += fmaxf(lo, 0.f) * s_w[2112 + 2 * hp]
               + fmaxf(hi, 0.f) * s_w[2112 + 2 * hp + 1];
        }
        if (valid) out[n] = o;
    }
}

extern "C" void kernel_launch(void* const* d_in, const int* in_sizes, int n_in,
                              void* d_out, int out_size) {
    const float* x    = (const float*)d_in[0];
    const int*   tick = (const int*)d_in[1];
    const float* mesa = (const float*)d_in[2];   // (M, T)
    const float* meta = (const float*)d_in[3];   // (S, M)
    const float* bias = (const float*)d_in[4];   // (S,)
    const float* base = (const float*)d_in[5];   // (S,)
    float* out = (float*)d_out;                  // (N, 1) float32

    k_prep<<<STATE_BLOCKS + SCAT_BLOCKS, 256>>>(tick, mesa, meta, bias, base);
    k_compute<<<TT, 64>>>(x, out);
}

// round 14
// speedup vs baseline: 1.0986x; 1.0986x over previous
#include <cuda_runtime.h>

// Problem constants
#define TT 1024   // T: tickers / states
#define MM 8      // M: mesa rank
#define NN 32768  // N: samples
#define DD 32     // D: input dim
#define HH 64     // H: hidden dim
#define SS 2177   // S = H*D + H + O*H + O
#define SP 2192   // padded state row stride (float4-aligned)
#define CAP 128   // bucket capacity per ticker

#define STATE_BLOCKS 288   // 32-ticker tiles x 9 dst-tiles (best measured)
#define SCAT_BLOCKS  32    // 32768 / (4 * 256)

// Scratch (__device__ globals; d_count zero-init at load, reset by k_compute)
__device__ int   d_count[TT];
__device__ int   d_bucket[TT * CAP];
__device__ float d_states[TT * SP];   // rows stored in PERMUTED (j*64+h) order

__device__ __forceinline__ unsigned long long fma2(
    unsigned long long a, unsigned long long b, unsigned long long c) {
    unsigned long long d;
    asm("fma.rn.f32x2 %0, %1, %2, %3;" : "=l"(d) : "l"(a), "l"(b), "l"(c));
    return d;
}
__device__ __forceinline__ unsigned long long dup2(float v) {
    unsigned long long d;
    asm("mov.b64 %0, {%1, %1};" : "=l"(d) : "f"(v));
    return d;
}

// ---------------------------------------------------------------------------
// k_prep: blocks [0,288) build effective states in PERMUTED layout:
//   row[d], d = j*64 + h  holds  w1_eff[h][j]  (d < 2048);
//   row[d] = state[d] for d in [2048,2177) (b1 | w2 | b2).
// blocks [288,320): bucket-scatter samples by ticker.
// ---------------------------------------------------------------------------
__global__ __launch_bounds__(256) void k_prep(
    const int*   __restrict__ ticker,
    const float* __restrict__ mesa,   // (M, T)
    const float* __restrict__ meta,   // (S, M)
    const float* __restrict__ bias,   // (S,)
    const float* __restrict__ base)   // (S,)
{
    int b   = blockIdx.x;
    int tid = threadIdx.x;

    if (b < STATE_BLOCKS) {
        __shared__ float4 sc4[32][2];     // mesa coeffs for 32 tickers
        int tt = b / 9, st = b % 9;
        int t0 = tt * 32;
        {
            int m = tid >> 5, i = tid & 31;
            ((float*)sc4)[i * 8 + m] = mesa[m * TT + t0 + i];
        }
        __syncthreads();

        int d = st * 256 + tid;           // destination index in permuted row
        int s;
        bool ok = true;
        if (d < 2048) {                   // w1: d = j*64 + h  <->  s = h*32 + j
            int h = d & 63, j = d >> 6;
            s = h * 32 + j;
        } else {
            s = d;
            ok = (d < SS);
        }
        if (ok) {
            const float4* m4 = (const float4*)(meta + s * MM);
            float4 a = m4[0], bq = m4[1];
            float bb = base[s] + bias[s];
#pragma unroll
            for (int i = 0; i < 32; i++) {
                float4 c0 = sc4[i][0];    // broadcast LDS.128
                float4 c1 = sc4[i][1];
                float v = bb
                    + c0.x * a.x + c0.y * a.y + c0.z * a.z + c0.w * a.w
                    + c1.x * bq.x + c1.y * bq.y + c1.z * bq.z + c1.w * bq.w;
                d_states[(t0 + i) * SP + d] = v;   // coalesced over d
            }
        }
    } else {
        int idx = (b - STATE_BLOCKS) * 256 + tid;
        int4 v = ((const int4*)ticker)[idx];
        int n0 = idx * 4;
        int p;
        p = atomicAdd(&d_count[v.x], 1); if (p < CAP) d_bucket[v.x * CAP + p] = n0;
        p = atomicAdd(&d_count[v.y], 1); if (p < CAP) d_bucket[v.y * CAP + p] = n0 + 1;
        p = atomicAdd(&d_count[v.z], 1); if (p < CAP) d_bucket[v.z * CAP + p] = n0 + 2;
        p = atomicAdd(&d_count[v.w], 1); if (p < CAP) d_bucket[v.w * CAP + p] = n0 + 3;
    }
}

// ---------------------------------------------------------------------------
// k_compute: 128-thread CTA = FOUR fully independent warps, one ticker each
// (warp w -> ticker blockIdx.x*4 + w). wid 0..3 puts one warp on each SMSP
// (the wid%4 placement rule): a single-warp CTA only ever feeds SMSP 0.
// Per warp: R5's sample-per-lane shape, but x lives in REGISTERS (8 float4
// gathered once per group) -> the j-loop is pure broadcast LDS.128 + FFMA2.
// No STS, no x-LDS, no shuffles, no block barriers.
// Per-warp smem row (2192 floats): [0,2048) w1 (j*64+h), [2048,2112) b1,
// [2112,2176) w2, [2176] b2.
// ---------------------------------------------------------------------------
__global__ __launch_bounds__(128) void k_compute(
    const float* __restrict__ x,
    float* __restrict__ out)
{
    __shared__ __align__(16) float s_w[4][2192];   // 35 KB, one row per warp

    int w    = threadIdx.x >> 5;
    int lane = threadIdx.x & 31;
    int t    = blockIdx.x * 4 + w;

    // Per-warp coalesced copy of its permuted state row (545 float4).
    const float4* row4 = (const float4*)(d_states + (size_t)t * SP);
    float4* sw4 = (float4*)s_w[w];
#pragma unroll
    for (int i = 0; i < 18; i++) {
        int idx = lane + i * 32;
        if (idx < 545) sw4[idx] = row4[idx];
    }

    int cnt = 0;
    if (lane == 0) { cnt = d_count[t]; d_count[t] = 0; }   // safe: 1 reader/t
    cnt = __shfl_sync(0xffffffffu, cnt, 0);
    if (cnt > CAP) cnt = CAP;
    __syncwarp();
    if (cnt == 0) return;

    const float* swf = s_w[w];
    const unsigned long long* b1p =
        (const unsigned long long*)(swf + 2048);   // b1 as f32x2 pairs
    const float2* w2p = (const float2*)(swf + 2112);
    float b2 = swf[2176];

    for (int base = 0; base < cnt; base += 32) {
        int idx = base + lane;
        bool valid = idx < cnt;
        int n = d_bucket[t * CAP + (valid ? idx : cnt - 1)];

        // Own sample's x row straight into registers (8 LDG.128).
        const float4* xr = (const float4*)(x + n * DD);
        float4 xv[8];
#pragma unroll
        for (int i = 0; i < 8; i++) xv[i] = xr[i];

        unsigned long long acc[32];
#pragma unroll
        for (int hp = 0; hp < 32; hp++) acc[hp] = b1p[hp];

#pragma unroll 4
        for (int jq = 0; jq < 8; jq++) {
            float xe[4] = {xv[jq].x, xv[jq].y, xv[jq].z, xv[jq].w};
#pragma unroll
            for (int e = 0; e < 4; e++) {
                int j = jq * 4 + e;
                unsigned long long xd = dup2(xe[e]);
                const ulonglong2* wr = (const ulonglong2*)(swf + j * 64);
#pragma unroll
                for (int hq = 0; hq < 16; hq++) {
                    ulonglong2 wv = wr[hq];           // broadcast LDS.128
                    acc[2 * hq]     = fma2(wv.x, xd, acc[2 * hq]);
                    acc[2 * hq + 1] = fma2(wv.y, xd, acc[2 * hq + 1]);
                }
            }
        }

        float o = b2;
#pragma unroll
        for (int hp = 0; hp < 32; hp++) {
            float lo = __uint_as_float((unsigned)(acc[hp] & 0xffffffffu));
            float hi = __uint_as_float((unsigned)(acc[hp] >> 32));
            float2 w2 = w2p[hp];                      // broadcast LDS.64
            o += fmaxf(lo, 0.f) * w2.x + fmaxf(hi, 0.f) * w2.y;
        }
        if (valid) out[n] = o;
    }
}

extern "C" void kernel_launch(void* const* d_in, const int* in_sizes, int n_in,
                              void* d_out, int out_size) {
    const float* x    = (const float*)d_in[0];
    const int*   tick = (const int*)d_in[1];
    const float* mesa = (const float*)d_in[2];   // (M, T)
    const float* meta = (const float*)d_in[3];   // (S, M)
    const float* bias = (const float*)d_in[4];   // (S,)
    const float* base = (const float*)d_in[5];   // (S,)
    float* out = (float*)d_out;                  // (N, 1) float32

    k_prep<<<STATE_BLOCKS + SCAT_BLOCKS, 256>>>(tick, mesa, meta, bias, base);
    k_compute<<<TT / 4, 128>>>(x, out);
}

// round 15
// speedup vs baseline: 1.2076x; 1.0992x over previous
#include <cuda_runtime.h>

// Problem constants
#define TT 1024   // T: tickers / states
#define MM 8      // M: mesa rank
#define NN 32768  // N: samples
#define DD 32     // D: input dim
#define HH 64     // H: hidden dim
#define SS 2177   // S = H*D + H + O*H + O
#define SP 2192   // padded state row stride (float4-aligned)
#define CAP 128   // bucket capacity per ticker

#define STATE_BLOCKS 288   // 32-ticker tiles x 9 dst-tiles (best measured)
#define SCAT_BLOCKS  32    // 32768 / (4 * 256)

// Scratch (__device__ globals; d_count zero-init at load, reset by k_compute)
__device__ int   d_count[TT];
__device__ int   d_bucket[TT * CAP];
__device__ float d_states[TT * SP];   // rows stored in PERMUTED (j*64+h) order

__device__ __forceinline__ unsigned long long fma2(
    unsigned long long a, unsigned long long b, unsigned long long c) {
    unsigned long long d;
    asm("fma.rn.f32x2 %0, %1, %2, %3;" : "=l"(d) : "l"(a), "l"(b), "l"(c));
    return d;
}
__device__ __forceinline__ unsigned long long dup2(float v) {
    unsigned long long d;
    asm("mov.b64 %0, {%1, %1};" : "=l"(d) : "f"(v));
    return d;
}

// ---------------------------------------------------------------------------
// k_prep (best-measured config, unchanged): blocks [0,288) build effective
// states in PERMUTED layout: row[d], d = j*64 + h holds w1_eff[h][j]
// (d < 2048); row[d] = state[d] for d in [2048,2177) (b1 | w2 | b2).
// blocks [288,320): bucket-scatter samples by ticker.
// ---------------------------------------------------------------------------
__global__ __launch_bounds__(256) void k_prep(
    const int*   __restrict__ ticker,
    const float* __restrict__ mesa,   // (M, T)
    const float* __restrict__ meta,   // (S, M)
    const float* __restrict__ bias,   // (S,)
    const float* __restrict__ base)   // (S,)
{
    int b   = blockIdx.x;
    int tid = threadIdx.x;

    if (b < STATE_BLOCKS) {
        __shared__ float4 sc4[32][2];     // mesa coeffs for 32 tickers
        int tt = b / 9, st = b % 9;
        int t0 = tt * 32;
        {
            int m = tid >> 5, i = tid & 31;
            ((float*)sc4)[i * 8 + m] = mesa[m * TT + t0 + i];
        }
        __syncthreads();

        int d = st * 256 + tid;           // destination index in permuted row
        int s;
        bool ok = true;
        if (d < 2048) {                   // w1: d = j*64 + h  <->  s = h*32 + j
            int h = d & 63, j = d >> 6;
            s = h * 32 + j;
        } else {
            s = d;
            ok = (d < SS);
        }
        if (ok) {
            const float4* m4 = (const float4*)(meta + s * MM);
            float4 a = m4[0], bq = m4[1];
            float bb = base[s] + bias[s];
#pragma unroll
            for (int i = 0; i < 32; i++) {
                float4 c0 = sc4[i][0];    // broadcast LDS.128
                float4 c1 = sc4[i][1];
                float v = bb
                    + c0.x * a.x + c0.y * a.y + c0.z * a.z + c0.w * a.w
                    + c1.x * bq.x + c1.y * bq.y + c1.z * bq.z + c1.w * bq.w;
                d_states[(t0 + i) * SP + d] = v;   // coalesced over d
            }
        }
    } else {
        int idx = (b - STATE_BLOCKS) * 256 + tid;
        int4 v = ((const int4*)ticker)[idx];
        int n0 = idx * 4;
        int p;
        p = atomicAdd(&d_count[v.x], 1); if (p < CAP) d_bucket[v.x * CAP + p] = n0;
        p = atomicAdd(&d_count[v.y], 1); if (p < CAP) d_bucket[v.y * CAP + p] = n0 + 1;
        p = atomicAdd(&d_count[v.z], 1); if (p < CAP) d_bucket[v.z * CAP + p] = n0 + 2;
        p = atomicAdd(&d_count[v.w], 1); if (p < CAP) d_bucket[v.w * CAP + p] = n0 + 3;
    }
}

// ---------------------------------------------------------------------------
// k_compute: R5 shape (one warp per ticker, sample-per-lane, 32 f32x2 hidden
// accumulators) with ONE change: all 32 xj values are hoisted into registers
// at group start (32 independent, conflict-free scalar LDS; bank=(lane+j)%32)
// so the j-loop has no x-load at the head of any dependency chain -- it is
// pure dup2(reg) + broadcast weight LDS.128 + FFMA2.
// smem floats: [0,2048) wint (j*64+h), [2048,2112) b1, [2112,2176) w2, 2176 b2.
// ---------------------------------------------------------------------------
__global__ __launch_bounds__(32) void k_compute(
    const float* __restrict__ x,
    float* __restrict__ out)
{
    __shared__ __align__(16) float s_w[2180];
    __shared__ float s_x[32 * 33];        // staged x, stride 33 (conflict-free)

    int t    = blockIdx.x;
    int lane = threadIdx.x;

    // Coalesced copy of the permuted state row (545 float4 -> 18 iterations).
    const float4* row4 = (const float4*)(d_states + (size_t)t * SP);
    float4* s_w4 = (float4*)s_w;
#pragma unroll
    for (int i = 0; i < 18; i++) {
        int idx = lane + i * 32;
        if (idx < 545) s_w4[idx] = row4[idx];
    }

    int cnt = 0;
    if (lane == 0) { cnt = d_count[t]; d_count[t] = 0; }
    cnt = __shfl_sync(0xffffffffu, cnt, 0);
    if (cnt > CAP) cnt = CAP;
    __syncwarp();
    if (cnt == 0) return;

    const unsigned long long* b1p =
        (const unsigned long long*)(s_w + 2048);     // b1 as f32x2 pairs
    float b2 = s_w[2176];

    for (int base = 0; base < cnt; base += 32) {
        int idx = base + lane;
        bool valid = idx < cnt;
        int n = d_bucket[t * CAP + (valid ? idx : cnt - 1)];

        __syncwarp();   // previous pass finished reading s_x
#pragma unroll
        for (int k = 0; k < 32; k++) {
            int nk = __shfl_sync(0xffffffffu, n, k);
            s_x[k * 33 + lane] = x[nk * DD + lane];   // coalesced 128B rows
        }
        __syncwarp();

        // Hoist own sample's 32 x values into registers: 32 independent
        // scalar LDS (bank (lane+j)%32, conflict-free), latency paid once.
        float xr[32];
#pragma unroll
        for (int j = 0; j < 32; j++) xr[j] = s_x[lane * 33 + j];

        unsigned long long acc[32];
#pragma unroll
        for (int hp = 0; hp < 32; hp++) acc[hp] = b1p[hp];

#pragma unroll 8
        for (int j = 0; j < 32; j++) {
            unsigned long long xd = dup2(xr[j]);      // register, no LDS
            const ulonglong2* wr = (const ulonglong2*)(s_w + j * 64);
#pragma unroll
            for (int hq = 0; hq < 16; hq++) {
                ulonglong2 w = wr[hq];                // broadcast LDS.128
                acc[2 * hq]     = fma2(w.x, xd, acc[2 * hq]);
                acc[2 * hq + 1] = fma2(w.y, xd, acc[2 * hq + 1]);
            }
        }

        float o = b2;
#pragma unroll
        for (int hp = 0; hp < 32; hp++) {
            float lo = __uint_as_float((unsigned)(acc[hp] & 0xffffffffu));
            float hi = __uint_as_float((unsigned)(acc[hp] >> 32));
            o += fmaxf(lo, 0.f) * s_w[2112 + 2 * hp]
               + fmaxf(hi, 0.f) * s_w[2112 + 2 * hp + 1];
        }
        if (valid) out[n] = o;
    }
}

extern "C" void kernel_launch(void* const* d_in, const int* in_sizes, int n_in,
                              void* d_out, int out_size) {
    const float* x    = (const float*)d_in[0];
    const int*   tick = (const int*)d_in[1];
    const float* mesa = (const float*)d_in[2];   // (M, T)
    const float* meta = (const float*)d_in[3];   // (S, M)
    const float* bias = (const float*)d_in[4];   // (S,)
    const float* base = (const float*)d_in[5];   // (S,)
    float* out = (float*)d_out;                  // (N, 1) float32

    k_prep<<<STATE_BLOCKS + SCAT_BLOCKS, 256>>>(tick, mesa, meta, bias, base);
    k_compute<<<TT, 32>>>(x, out);
}